// round 12
// baseline (speedup 1.0000x reference)
#include <cuda_runtime.h>

#define N_NODES 50000
#define N_EDGES 800000
#define D_IN 64
#define D_OUT 64
#define E_DIM 32
#define NK 96
#define BN_EPS 1e-5f

typedef unsigned long long ull;

#define FMA2(acc, a, b) \
    asm("fma.rn.f32x2 %0, %1, %2, %3;" : "=l"(acc) : "l"(a), "l"(b), "l"(acc))
#define PACK2(out, lo, hi) \
    asm("mov.b64 %0, {%1, %2};" : "=l"(out) : "f"(lo), "f"(hi))
#define UNPACK2(lo, hi, in) \
    asm("mov.b64 {%0, %1}, %2;" : "=f"(lo), "=f"(hi) : "l"(in))

// ---------------- scratch ----------------
__device__ __align__(16) float g_aggX[N_NODES * D_IN];
__device__ __align__(16) float g_aggE[N_NODES * E_DIM];
__device__ __align__(16) float g_h[N_NODES * D_OUT];
__device__ int g_cnt[N_NODES];
__device__ int g_rowstart[N_NODES + 1];
__device__ int g_cursor[N_NODES];
__device__ int g_esrc[N_EDGES];
__device__ __align__(16) float g_sum[D_OUT];
__device__ __align__(16) float g_sumsq[D_OUT];
__device__ __align__(8) float2 g_WpA[48 * 32];   // (Wall[2j][d], Wall[2j+1][d]) d=lane
__device__ __align__(8) float2 g_WpB[48 * 32];   // d = lane+32
__device__ __align__(8) float2 g_W2pA[32 * 32];
__device__ __align__(8) float2 g_W2pB[32 * 32];
__device__ __align__(16) float g_c2[D_OUT];      // be @ W1
__device__ __align__(16) float g_scale[D_OUT];
__device__ __align__(16) float g_shift[D_OUT];

// ---------------- kernel 0: zero ----------------
__global__ void zero_kernel() {
    int idx = blockIdx.x * blockDim.x + threadIdx.x;
    int stride = gridDim.x * blockDim.x;
    float4 z = make_float4(0.f, 0.f, 0.f, 0.f);
    for (int i = idx; i < N_NODES * (E_DIM / 4); i += stride) ((float4*)g_aggE)[i] = z;
    for (int i = idx; i < N_NODES; i += stride) g_cnt[i] = 0;
    if (idx < D_OUT) { g_sum[idx] = 0.f; g_sumsq[idx] = 0.f; }
}

// ---------------- kernel 1: prep packed weights ----------------
__global__ void prep_kernel(const float* __restrict__ We,
                            const float* __restrict__ be,
                            const float* __restrict__ W1,
                            const float* __restrict__ W2) {
    __shared__ float W1s[D_IN * D_OUT];
    __shared__ float C1s[E_DIM * D_OUT];
    int tid = threadIdx.x;
    for (int i = tid; i < D_IN * D_OUT; i += 256) W1s[i] = W1[i];
    __syncthreads();
    for (int i = tid; i < E_DIM * D_OUT; i += 256) {
        int kk = i >> 6, d = i & 63;
        float s = 0.f;
        #pragma unroll 8
        for (int m = 0; m < D_IN; m++) s += We[kk * D_IN + m] * W1s[m * D_OUT + d];
        C1s[i] = s;
    }
    __syncthreads();
    // pack node_h weights: 48 k-pairs x 32 lanes
    for (int i = tid; i < 48 * 32; i += 256) {
        int k2 = i >> 5, l = i & 31;
        int ka = 2 * k2, kb = 2 * k2 + 1;
        float a0 = (ka < 64) ? W1s[ka * 64 + l] : C1s[(ka - 64) * 64 + l];
        float a1 = (kb < 64) ? W1s[kb * 64 + l] : C1s[(kb - 64) * 64 + l];
        g_WpA[i] = make_float2(a0, a1);
        float b0 = (ka < 64) ? W1s[ka * 64 + l + 32] : C1s[(ka - 64) * 64 + l + 32];
        float b1v = (kb < 64) ? W1s[kb * 64 + l + 32] : C1s[(kb - 64) * 64 + l + 32];
        g_WpB[i] = make_float2(b0, b1v);
    }
    // pack node_out weights: 32 k-pairs x 32 lanes
    for (int i = tid; i < 32 * 32; i += 256) {
        int k2 = i >> 5, l = i & 31;
        g_W2pA[i] = make_float2(W2[(2 * k2) * 64 + l], W2[(2 * k2 + 1) * 64 + l]);
        g_W2pB[i] = make_float2(W2[(2 * k2) * 64 + l + 32], W2[(2 * k2 + 1) * 64 + l + 32]);
    }
    if (tid < D_OUT) {
        float s = 0.f;
        #pragma unroll 8
        for (int m = 0; m < D_IN; m++) s += be[m] * W1s[m * D_OUT + tid];
        g_c2[tid] = s;
    }
}

// ---------------- CSR build ----------------
__global__ void hist_kernel(const int* __restrict__ ei) {
    int e = blockIdx.x * blockDim.x + threadIdx.x;
    if (e < N_EDGES) atomicAdd(&g_cnt[ei[N_EDGES + e]], 1);
}

// single-launch scan: 1 block x 1024, chunk of 49 nodes per thread
__global__ void scan_all_kernel() {
    __shared__ int warpsum[32];
    int t = threadIdx.x;
    const int CH = 49;
    int beg = t * CH;
    int end = beg + CH; if (end > N_NODES) end = N_NODES;
    int loc = 0;
    for (int i = beg; i < end; i++) loc += g_cnt[i];
    int lane = t & 31, w = t >> 5;
    int v = loc;
    #pragma unroll
    for (int off = 1; off < 32; off <<= 1) {
        int y = __shfl_up_sync(0xffffffffu, v, off);
        if (lane >= off) v += y;
    }
    if (lane == 31) warpsum[w] = v;
    __syncthreads();
    if (w == 0) {
        int s = warpsum[lane];
        #pragma unroll
        for (int off = 1; off < 32; off <<= 1) {
            int y = __shfl_up_sync(0xffffffffu, s, off);
            if (lane >= off) s += y;
        }
        warpsum[lane] = s;
    }
    __syncthreads();
    int base = v - loc + ((w > 0) ? warpsum[w - 1] : 0);
    for (int i = beg; i < end; i++) {
        g_rowstart[i] = base;
        g_cursor[i] = base;
        base += g_cnt[i];
    }
    if (t == 0) g_rowstart[N_NODES] = N_EDGES;
}

__global__ void scatter_kernel(const int* __restrict__ ei) {
    int e = blockIdx.x * blockDim.x + threadIdx.x;
    if (e >= N_EDGES) return;
    int dst = ei[N_EDGES + e];
    int pos = atomicAdd(&g_cursor[dst], 1);
    g_esrc[pos] = ei[e];
}

// ---------------- ea scatter: streaming reads + float4 REDs (R11-proven) ------
__global__ void ea_kernel(const int* __restrict__ ei,
                          const float4* __restrict__ ea4) {
    int gwarp = (blockIdx.x * blockDim.x + threadIdx.x) >> 5;
    int lane = threadIdx.x & 31;
    int e = gwarp * 4 + (lane >> 3);
    if (e >= N_EDGES) return;
    int li = lane & 7;
    int dst = __ldg(&ei[N_EDGES + e]);
    float4 av = __ldg(&ea4[(size_t)e * (E_DIM / 4) + li]);
    atomicAdd(((float4*)(g_aggE + (size_t)dst * E_DIM)) + li, av);
}

// ---------------- gather x (R11-proven) ----------------
__global__ void gather_x_kernel(const float4* __restrict__ x4) {
    int gw = (blockIdx.x * blockDim.x + threadIdx.x) >> 5;
    if (gw >= N_NODES) return;
    int lane = threadIdx.x & 31;
    int half = lane >> 4, li = lane & 15;
    int start = g_rowstart[gw], end = g_rowstart[gw + 1];
    float4 acc = make_float4(0.f, 0.f, 0.f, 0.f);
    int p = start;
    for (; p + 8 <= end; p += 8) {
        int s0 = __ldg(&g_esrc[p + half]);
        int s1 = __ldg(&g_esrc[p + 2 + half]);
        int s2 = __ldg(&g_esrc[p + 4 + half]);
        int s3 = __ldg(&g_esrc[p + 6 + half]);
        float4 v0 = __ldg(&x4[(size_t)s0 * 16 + li]);
        float4 v1 = __ldg(&x4[(size_t)s1 * 16 + li]);
        float4 v2 = __ldg(&x4[(size_t)s2 * 16 + li]);
        float4 v3 = __ldg(&x4[(size_t)s3 * 16 + li]);
        acc.x += (v0.x + v1.x) + (v2.x + v3.x);
        acc.y += (v0.y + v1.y) + (v2.y + v3.y);
        acc.z += (v0.z + v1.z) + (v2.z + v3.z);
        acc.w += (v0.w + v1.w) + (v2.w + v3.w);
    }
    for (int e = p + half; e < end; e += 2) {
        int s = __ldg(&g_esrc[e]);
        float4 v = __ldg(&x4[(size_t)s * 16 + li]);
        acc.x += v.x; acc.y += v.y; acc.z += v.z; acc.w += v.w;
    }
    acc.x += __shfl_down_sync(0xffffffffu, acc.x, 16);
    acc.y += __shfl_down_sync(0xffffffffu, acc.y, 16);
    acc.z += __shfl_down_sync(0xffffffffu, acc.z, 16);
    acc.w += __shfl_down_sync(0xffffffffu, acc.w, 16);
    if (half == 0) ((float4*)g_aggX)[(size_t)gw * 16 + li] = acc;
}

// ---------------- node_h: R3 skeleton, even/odd-k FFMA2 inner loop -------------
// 8 warps/block, 8 rows/warp, lane owns dims (lane, lane+32).
// acc pairs hold (even-k partial, odd-k partial); final h = lo + hi.
__global__ __launch_bounds__(256, 3) void node_h_kernel(const float* __restrict__ x,
                                                        const float* __restrict__ b1) {
    __shared__ __align__(8) float2 WpA[48 * 32];     // 12KB
    __shared__ __align__(8) float2 WpB[48 * 32];     // 12KB
    __shared__ __align__(16) float st[8][8 * NK];    // 24KB
    __shared__ float c2s[64], b1s[64];
    __shared__ float bsum[64], bsq[64];

    int tid = threadIdx.x;
    for (int i = tid; i < 48 * 32; i += 256) { WpA[i] = g_WpA[i]; WpB[i] = g_WpB[i]; }
    if (tid < 64) { c2s[tid] = g_c2[tid]; b1s[tid] = b1[tid]; bsum[tid] = 0.f; bsq[tid] = 0.f; }
    __syncthreads();

    int warp = tid >> 5, lane = tid & 31;
    float c2A = c2s[lane], c2B = c2s[lane + 32];
    float b1A = b1s[lane], b1B = b1s[lane + 32];
    float s0 = 0.f, q0 = 0.f, s1 = 0.f, q1 = 0.f;

    int nGroups = (N_NODES + 63) / 64;   // 782
    for (int g = blockIdx.x; g < nGroups; g += gridDim.x) {
        int rowBase = g * 64 + warp * 8;
        #pragma unroll
        for (int r = 0; r < 8; r++) {
            int row = rowBase + r;
            if (row < N_NODES) {
                if (lane < 16) {
                    float4 a = ((const float4*)g_aggX)[(size_t)row * 16 + lane];
                    float4 xv = __ldg(&((const float4*)x)[(size_t)row * 16 + lane]);
                    a.x += xv.x; a.y += xv.y; a.z += xv.z; a.w += xv.w;
                    *(float4*)&st[warp][r * NK + lane * 4] = a;
                } else if (lane < 24) {
                    *(float4*)&st[warp][r * NK + 64 + (lane - 16) * 4] =
                        ((const float4*)g_aggE)[(size_t)row * 8 + (lane - 16)];
                }
            }
        }
        __syncwarp();

        ull accA[8], accB[8];
        #pragma unroll
        for (int r = 0; r < 8; r++) {
            int row = rowBase + r;
            float dg = 0.f;
            if (row < N_NODES) dg = (float)(g_rowstart[row + 1] - g_rowstart[row]);
            PACK2(accA[r], dg * c2A + b1A, 0.f);
            PACK2(accB[r], dg * c2B + b1B, 0.f);
        }
        #pragma unroll 4
        for (int kq = 0; kq < NK / 4; kq++) {
            ull wA0 = *(const ull*)&WpA[(2 * kq) * 32 + lane];
            ull wB0 = *(const ull*)&WpB[(2 * kq) * 32 + lane];
            ull wA1 = *(const ull*)&WpA[(2 * kq + 1) * 32 + lane];
            ull wB1 = *(const ull*)&WpB[(2 * kq + 1) * 32 + lane];
            #pragma unroll
            for (int r = 0; r < 8; r++) {
                float4 a4 = *(const float4*)&st[warp][r * NK + kq * 4];
                ull a01, a23;
                PACK2(a01, a4.x, a4.y);
                PACK2(a23, a4.z, a4.w);
                FMA2(accA[r], a01, wA0);
                FMA2(accB[r], a01, wB0);
                FMA2(accA[r], a23, wA1);
                FMA2(accB[r], a23, wB1);
            }
        }
        #pragma unroll
        for (int r = 0; r < 8; r++) {
            int row = rowBase + r;
            if (row < N_NODES) {
                float lA, hA, lB, hB;
                UNPACK2(lA, hA, accA[r]);
                UNPACK2(lB, hB, accB[r]);
                float h0 = lA + hA, h1 = lB + hB;
                g_h[(size_t)row * 64 + lane] = h0;
                g_h[(size_t)row * 64 + 32 + lane] = h1;
                s0 += h0; q0 += h0 * h0;
                s1 += h1; q1 += h1 * h1;
            }
        }
        __syncwarp();
    }
    atomicAdd(&bsum[lane], s0);      atomicAdd(&bsq[lane], q0);
    atomicAdd(&bsum[lane + 32], s1); atomicAdd(&bsq[lane + 32], q1);
    __syncthreads();
    if (tid < 64) { atomicAdd(&g_sum[tid], bsum[tid]); atomicAdd(&g_sumsq[tid], bsq[tid]); }
}

// ---------------- bn finalize ----------------
__global__ void bn_kernel(const float* __restrict__ gamma,
                          const float* __restrict__ beta) {
    int d = threadIdx.x;
    float n = (float)N_NODES;
    float mean = g_sum[d] / n;
    float var = g_sumsq[d] / n - mean * mean;
    float rstd = rsqrtf(var + BN_EPS);
    float sc = gamma[d] * rstd;
    g_scale[d] = sc;
    g_shift[d] = beta[d] - mean * sc;
}

// ---------------- node_out: same scheme, k=64, BN+ReLU fused into staging ------
__global__ __launch_bounds__(256, 3) void node_out_kernel(const float* __restrict__ b2,
                                                          float* __restrict__ out) {
    __shared__ __align__(8) float2 WpA[32 * 32];     // 8KB
    __shared__ __align__(8) float2 WpB[32 * 32];     // 8KB
    __shared__ __align__(16) float st[8][8 * 64];    // 16KB
    __shared__ __align__(16) float scs[64], shs[64];
    __shared__ float b2s[64];

    int tid = threadIdx.x;
    for (int i = tid; i < 32 * 32; i += 256) { WpA[i] = g_W2pA[i]; WpB[i] = g_W2pB[i]; }
    if (tid < 64) { scs[tid] = g_scale[tid]; shs[tid] = g_shift[tid]; b2s[tid] = b2[tid]; }
    __syncthreads();

    int warp = tid >> 5, lane = tid & 31;
    float b2A = b2s[lane], b2B = b2s[lane + 32];

    int nGroups = (N_NODES + 63) / 64;
    for (int g = blockIdx.x; g < nGroups; g += gridDim.x) {
        int rowBase = g * 64 + warp * 8;
        #pragma unroll
        for (int r = 0; r < 8; r++) {
            int row = rowBase + r;
            if (row < N_NODES && lane < 16) {
                float4 hv = ((const float4*)g_h)[(size_t)row * 16 + lane];
                float4 sc = ((const float4*)scs)[lane];
                float4 sh = ((const float4*)shs)[lane];
                float4 v;
                v.x = fmaxf(0.f, hv.x * sc.x + sh.x);
                v.y = fmaxf(0.f, hv.y * sc.y + sh.y);
                v.z = fmaxf(0.f, hv.z * sc.z + sh.z);
                v.w = fmaxf(0.f, hv.w * sc.w + sh.w);
                *(float4*)&st[warp][r * 64 + lane * 4] = v;
            }
        }
        __syncwarp();

        ull accA[8], accB[8];
        #pragma unroll
        for (int r = 0; r < 8; r++) {
            PACK2(accA[r], b2A, 0.f);
            PACK2(accB[r], b2B, 0.f);
        }
        #pragma unroll 4
        for (int kq = 0; kq < 16; kq++) {
            ull wA0 = *(const ull*)&WpA[(2 * kq) * 32 + lane];
            ull wB0 = *(const ull*)&WpB[(2 * kq) * 32 + lane];
            ull wA1 = *(const ull*)&WpA[(2 * kq + 1) * 32 + lane];
            ull wB1 = *(const ull*)&WpB[(2 * kq + 1) * 32 + lane];
            #pragma unroll
            for (int r = 0; r < 8; r++) {
                float4 a4 = *(const float4*)&st[warp][r * 64 + kq * 4];
                ull a01, a23;
                PACK2(a01, a4.x, a4.y);
                PACK2(a23, a4.z, a4.w);
                FMA2(accA[r], a01, wA0);
                FMA2(accB[r], a01, wB0);
                FMA2(accA[r], a23, wA1);
                FMA2(accB[r], a23, wB1);
            }
        }
        #pragma unroll
        for (int r = 0; r < 8; r++) {
            int row = rowBase + r;
            if (row < N_NODES) {
                float lA, hA, lB, hB;
                UNPACK2(lA, hA, accA[r]);
                UNPACK2(lB, hB, accB[r]);
                out[(size_t)row * 64 + lane] = lA + hA;
                out[(size_t)row * 64 + 32 + lane] = lB + hB;
            }
        }
        __syncwarp();
    }
}

// ---------------- launch ----------------
extern "C" void kernel_launch(void* const* d_in, const int* in_sizes, int n_in,
                              void* d_out, int out_size) {
    const float* x     = (const float*)d_in[0];
    const int* ei      = (const int*)d_in[1];
    const float* ea    = (const float*)d_in[2];
    const float* We    = (const float*)d_in[3];
    const float* be    = (const float*)d_in[4];
    const float* W1    = (const float*)d_in[5];
    const float* b1    = (const float*)d_in[6];
    const float* gamma = (const float*)d_in[7];
    const float* beta  = (const float*)d_in[8];
    const float* W2    = (const float*)d_in[9];
    const float* b2    = (const float*)d_in[10];
    float* out         = (float*)d_out;

    zero_kernel<<<1024, 256>>>();
    prep_kernel<<<1, 256>>>(We, be, W1, W2);

    hist_kernel<<<(N_EDGES + 255) / 256, 256>>>(ei);
    scan_all_kernel<<<1, 1024>>>();
    scatter_kernel<<<(N_EDGES + 255) / 256, 256>>>(ei);

    ea_kernel<<<(N_EDGES / 4 + 7) / 8, 256>>>(ei, (const float4*)ea);
    gather_x_kernel<<<(N_NODES * 32 + 255) / 256, 256>>>((const float4*)x);

    node_h_kernel<<<444, 256>>>(x, b1);
    bn_kernel<<<1, 64>>>(gamma, beta);
    node_out_kernel<<<444, 256>>>(b2, out);
}

// round 13
// speedup vs baseline: 1.4139x; 1.4139x over previous
#include <cuda_runtime.h>

#define N_NODES 50000
#define N_EDGES 800000
#define D_IN 64
#define D_OUT 64
#define E_DIM 32
#define NK 96
#define BN_EPS 1e-5f

typedef unsigned long long ull;

#define FMA2(acc, a, b) \
    asm("fma.rn.f32x2 %0, %1, %2, %3;" : "=l"(acc) : "l"(a), "l"(b), "l"(acc))
#define PACK2(out, lo, hi) \
    asm("mov.b64 %0, {%1, %2};" : "=l"(out) : "f"(lo), "f"(hi))
#define UNPACK2(lo, hi, in) \
    asm("mov.b64 {%0, %1}, %2;" : "=f"(lo), "=f"(hi) : "l"(in))

// ---------------- scratch ----------------
__device__ __align__(16) float g_aggX[N_NODES * D_IN];
__device__ __align__(16) float g_aggE[N_NODES * E_DIM];
__device__ __align__(16) float g_h[N_NODES * D_OUT];
__device__ int g_cnt[N_NODES];
__device__ int g_locpre[65536];
__device__ int g_part[256];
__device__ int g_partoff[256];
__device__ int g_rowstart[N_NODES + 1];
__device__ int g_cursor[N_NODES];
__device__ int g_esrc[N_EDGES];
__device__ __align__(16) float g_sum[D_OUT];
__device__ __align__(16) float g_sumsq[D_OUT];
__device__ __align__(8) float2 g_WpA[48 * 32];   // (Wall[2j][d], Wall[2j+1][d]) d=lane
__device__ __align__(8) float2 g_WpB[48 * 32];   // d = lane+32
__device__ __align__(8) float2 g_W2pA[32 * 32];
__device__ __align__(8) float2 g_W2pB[32 * 32];
__device__ __align__(16) float g_c2[D_OUT];      // be @ W1
__device__ __align__(16) float g_scale[D_OUT];
__device__ __align__(16) float g_shift[D_OUT];

// ---------------- kernel 0: zero ----------------
__global__ void zero_kernel() {
    int idx = blockIdx.x * blockDim.x + threadIdx.x;
    int stride = gridDim.x * blockDim.x;
    float4 z = make_float4(0.f, 0.f, 0.f, 0.f);
    for (int i = idx; i < N_NODES * (E_DIM / 4); i += stride) ((float4*)g_aggE)[i] = z;
    for (int i = idx; i < N_NODES; i += stride) g_cnt[i] = 0;
    if (idx < D_OUT) { g_sum[idx] = 0.f; g_sumsq[idx] = 0.f; }
}

// ---------------- kernel 1: prep packed weights (R12-proven) -------------------
__global__ void prep_kernel(const float* __restrict__ We,
                            const float* __restrict__ be,
                            const float* __restrict__ W1,
                            const float* __restrict__ W2) {
    __shared__ float W1s[D_IN * D_OUT];
    __shared__ float C1s[E_DIM * D_OUT];
    int tid = threadIdx.x;
    for (int i = tid; i < D_IN * D_OUT; i += 256) W1s[i] = W1[i];
    __syncthreads();
    for (int i = tid; i < E_DIM * D_OUT; i += 256) {
        int kk = i >> 6, d = i & 63;
        float s = 0.f;
        #pragma unroll 8
        for (int m = 0; m < D_IN; m++) s += We[kk * D_IN + m] * W1s[m * D_OUT + d];
        C1s[i] = s;
    }
    __syncthreads();
    for (int i = tid; i < 48 * 32; i += 256) {
        int k2 = i >> 5, l = i & 31;
        int ka = 2 * k2, kb = 2 * k2 + 1;
        float a0 = (ka < 64) ? W1s[ka * 64 + l] : C1s[(ka - 64) * 64 + l];
        float a1 = (kb < 64) ? W1s[kb * 64 + l] : C1s[(kb - 64) * 64 + l];
        g_WpA[i] = make_float2(a0, a1);
        float b0 = (ka < 64) ? W1s[ka * 64 + l + 32] : C1s[(ka - 64) * 64 + l + 32];
        float b1v = (kb < 64) ? W1s[kb * 64 + l + 32] : C1s[(kb - 64) * 64 + l + 32];
        g_WpB[i] = make_float2(b0, b1v);
    }
    for (int i = tid; i < 32 * 32; i += 256) {
        int k2 = i >> 5, l = i & 31;
        g_W2pA[i] = make_float2(W2[(2 * k2) * 64 + l], W2[(2 * k2 + 1) * 64 + l]);
        g_W2pB[i] = make_float2(W2[(2 * k2) * 64 + l + 32], W2[(2 * k2 + 1) * 64 + l + 32]);
    }
    if (tid < D_OUT) {
        float s = 0.f;
        #pragma unroll 8
        for (int m = 0; m < D_IN; m++) s += be[m] * W1s[m * D_OUT + tid];
        g_c2[tid] = s;
    }
}

// ---------------- CSR build (R11-proven 3-kernel scan chain) -------------------
__global__ void hist_kernel(const int* __restrict__ ei) {
    int e = blockIdx.x * blockDim.x + threadIdx.x;
    if (e < N_EDGES) atomicAdd(&g_cnt[ei[N_EDGES + e]], 1);
}

__global__ void scan1_kernel() {   // 256 blocks x 256
    __shared__ int sd[256];
    int t = threadIdx.x;
    int g = blockIdx.x * 256 + t;
    int v = (g < N_NODES) ? g_cnt[g] : 0;
    sd[t] = v;
    __syncthreads();
    #pragma unroll
    for (int off = 1; off < 256; off <<= 1) {
        int y = (t >= off) ? sd[t - off] : 0;
        __syncthreads();
        sd[t] += y;
        __syncthreads();
    }
    g_locpre[g] = sd[t] - v;
    if (t == 255) g_part[blockIdx.x] = sd[255];
}

__global__ void scan2_kernel() {   // 1 block x 256
    __shared__ int sd[256];
    int t = threadIdx.x;
    int v = g_part[t];
    sd[t] = v;
    __syncthreads();
    #pragma unroll
    for (int off = 1; off < 256; off <<= 1) {
        int y = (t >= off) ? sd[t - off] : 0;
        __syncthreads();
        sd[t] += y;
        __syncthreads();
    }
    g_partoff[t] = sd[t] - v;
}

__global__ void scan3_kernel() {   // 256 blocks x 256
    int t = threadIdx.x;
    int g = blockIdx.x * 256 + t;
    if (g < N_NODES) {
        int rs = g_locpre[g] + g_partoff[blockIdx.x];
        g_rowstart[g] = rs;
        g_cursor[g] = rs;
    }
    if (g == 0) g_rowstart[N_NODES] = N_EDGES;
}

__global__ void scatter_kernel(const int* __restrict__ ei) {
    int e = blockIdx.x * blockDim.x + threadIdx.x;
    if (e >= N_EDGES) return;
    int dst = ei[N_EDGES + e];
    int pos = atomicAdd(&g_cursor[dst], 1);
    g_esrc[pos] = ei[e];
}

// ---------------- ea scatter: streaming reads + float4 REDs (R11-proven) ------
__global__ void ea_kernel(const int* __restrict__ ei,
                          const float4* __restrict__ ea4) {
    int gwarp = (blockIdx.x * blockDim.x + threadIdx.x) >> 5;
    int lane = threadIdx.x & 31;
    int e = gwarp * 4 + (lane >> 3);
    if (e >= N_EDGES) return;
    int li = lane & 7;
    int dst = __ldg(&ei[N_EDGES + e]);
    float4 av = __ldg(&ea4[(size_t)e * (E_DIM / 4) + li]);
    atomicAdd(((float4*)(g_aggE + (size_t)dst * E_DIM)) + li, av);
}

// ---------------- gather x (R11-proven) ----------------
__global__ void gather_x_kernel(const float4* __restrict__ x4) {
    int gw = (blockIdx.x * blockDim.x + threadIdx.x) >> 5;
    if (gw >= N_NODES) return;
    int lane = threadIdx.x & 31;
    int half = lane >> 4, li = lane & 15;
    int start = g_rowstart[gw], end = g_rowstart[gw + 1];
    float4 acc = make_float4(0.f, 0.f, 0.f, 0.f);
    int p = start;
    for (; p + 8 <= end; p += 8) {
        int s0 = __ldg(&g_esrc[p + half]);
        int s1 = __ldg(&g_esrc[p + 2 + half]);
        int s2 = __ldg(&g_esrc[p + 4 + half]);
        int s3 = __ldg(&g_esrc[p + 6 + half]);
        float4 v0 = __ldg(&x4[(size_t)s0 * 16 + li]);
        float4 v1 = __ldg(&x4[(size_t)s1 * 16 + li]);
        float4 v2 = __ldg(&x4[(size_t)s2 * 16 + li]);
        float4 v3 = __ldg(&x4[(size_t)s3 * 16 + li]);
        acc.x += (v0.x + v1.x) + (v2.x + v3.x);
        acc.y += (v0.y + v1.y) + (v2.y + v3.y);
        acc.z += (v0.z + v1.z) + (v2.z + v3.z);
        acc.w += (v0.w + v1.w) + (v2.w + v3.w);
    }
    for (int e = p + half; e < end; e += 2) {
        int s = __ldg(&g_esrc[e]);
        float4 v = __ldg(&x4[(size_t)s * 16 + li]);
        acc.x += v.x; acc.y += v.y; acc.z += v.z; acc.w += v.w;
    }
    acc.x += __shfl_down_sync(0xffffffffu, acc.x, 16);
    acc.y += __shfl_down_sync(0xffffffffu, acc.y, 16);
    acc.z += __shfl_down_sync(0xffffffffu, acc.z, 16);
    acc.w += __shfl_down_sync(0xffffffffu, acc.w, 16);
    if (half == 0) ((float4*)g_aggX)[(size_t)gw * 16 + li] = acc;
}

// ---------------- node_h: R12-proven FFMA2 inner loop --------------------------
__global__ __launch_bounds__(256, 3) void node_h_kernel(const float* __restrict__ x,
                                                        const float* __restrict__ b1) {
    __shared__ __align__(8) float2 WpA[48 * 32];     // 12KB
    __shared__ __align__(8) float2 WpB[48 * 32];     // 12KB
    __shared__ __align__(16) float st[8][8 * NK];    // 24KB
    __shared__ float c2s[64], b1s[64];
    __shared__ float bsum[64], bsq[64];

    int tid = threadIdx.x;
    for (int i = tid; i < 48 * 32; i += 256) { WpA[i] = g_WpA[i]; WpB[i] = g_WpB[i]; }
    if (tid < 64) { c2s[tid] = g_c2[tid]; b1s[tid] = b1[tid]; bsum[tid] = 0.f; bsq[tid] = 0.f; }
    __syncthreads();

    int warp = tid >> 5, lane = tid & 31;
    float c2A = c2s[lane], c2B = c2s[lane + 32];
    float b1A = b1s[lane], b1B = b1s[lane + 32];
    float s0 = 0.f, q0 = 0.f, s1 = 0.f, q1 = 0.f;

    int nGroups = (N_NODES + 63) / 64;   // 782
    for (int g = blockIdx.x; g < nGroups; g += gridDim.x) {
        int rowBase = g * 64 + warp * 8;
        #pragma unroll
        for (int r = 0; r < 8; r++) {
            int row = rowBase + r;
            if (row < N_NODES) {
                if (lane < 16) {
                    float4 a = ((const float4*)g_aggX)[(size_t)row * 16 + lane];
                    float4 xv = __ldg(&((const float4*)x)[(size_t)row * 16 + lane]);
                    a.x += xv.x; a.y += xv.y; a.z += xv.z; a.w += xv.w;
                    *(float4*)&st[warp][r * NK + lane * 4] = a;
                } else if (lane < 24) {
                    *(float4*)&st[warp][r * NK + 64 + (lane - 16) * 4] =
                        ((const float4*)g_aggE)[(size_t)row * 8 + (lane - 16)];
                }
            }
        }
        __syncwarp();

        ull accA[8], accB[8];
        #pragma unroll
        for (int r = 0; r < 8; r++) {
            int row = rowBase + r;
            float dg = 0.f;
            if (row < N_NODES) dg = (float)(g_rowstart[row + 1] - g_rowstart[row]);
            PACK2(accA[r], dg * c2A + b1A, 0.f);
            PACK2(accB[r], dg * c2B + b1B, 0.f);
        }
        #pragma unroll 4
        for (int kq = 0; kq < NK / 4; kq++) {
            ull wA0 = *(const ull*)&WpA[(2 * kq) * 32 + lane];
            ull wB0 = *(const ull*)&WpB[(2 * kq) * 32 + lane];
            ull wA1 = *(const ull*)&WpA[(2 * kq + 1) * 32 + lane];
            ull wB1 = *(const ull*)&WpB[(2 * kq + 1) * 32 + lane];
            #pragma unroll
            for (int r = 0; r < 8; r++) {
                float4 a4 = *(const float4*)&st[warp][r * NK + kq * 4];
                ull a01, a23;
                PACK2(a01, a4.x, a4.y);
                PACK2(a23, a4.z, a4.w);
                FMA2(accA[r], a01, wA0);
                FMA2(accB[r], a01, wB0);
                FMA2(accA[r], a23, wA1);
                FMA2(accB[r], a23, wB1);
            }
        }
        #pragma unroll
        for (int r = 0; r < 8; r++) {
            int row = rowBase + r;
            if (row < N_NODES) {
                float lA, hA, lB, hB;
                UNPACK2(lA, hA, accA[r]);
                UNPACK2(lB, hB, accB[r]);
                float h0 = lA + hA, h1 = lB + hB;
                g_h[(size_t)row * 64 + lane] = h0;
                g_h[(size_t)row * 64 + 32 + lane] = h1;
                s0 += h0; q0 += h0 * h0;
                s1 += h1; q1 += h1 * h1;
            }
        }
        __syncwarp();
    }
    atomicAdd(&bsum[lane], s0);      atomicAdd(&bsq[lane], q0);
    atomicAdd(&bsum[lane + 32], s1); atomicAdd(&bsq[lane + 32], q1);
    __syncthreads();
    if (tid < 64) { atomicAdd(&g_sum[tid], bsum[tid]); atomicAdd(&g_sumsq[tid], bsq[tid]); }
}

// ---------------- bn finalize ----------------
__global__ void bn_kernel(const float* __restrict__ gamma,
                          const float* __restrict__ beta) {
    int d = threadIdx.x;
    float n = (float)N_NODES;
    float mean = g_sum[d] / n;
    float var = g_sumsq[d] / n - mean * mean;
    float rstd = rsqrtf(var + BN_EPS);
    float sc = gamma[d] * rstd;
    g_scale[d] = sc;
    g_shift[d] = beta[d] - mean * sc;
}

// ---------------- node_out: R12-proven FFMA2 ----------------
__global__ __launch_bounds__(256, 3) void node_out_kernel(const float* __restrict__ b2,
                                                          float* __restrict__ out) {
    __shared__ __align__(8) float2 WpA[32 * 32];     // 8KB
    __shared__ __align__(8) float2 WpB[32 * 32];     // 8KB
    __shared__ __align__(16) float st[8][8 * 64];    // 16KB
    __shared__ __align__(16) float scs[64], shs[64];
    __shared__ float b2s[64];

    int tid = threadIdx.x;
    for (int i = tid; i < 32 * 32; i += 256) { WpA[i] = g_W2pA[i]; WpB[i] = g_W2pB[i]; }
    if (tid < 64) { scs[tid] = g_scale[tid]; shs[tid] = g_shift[tid]; b2s[tid] = b2[tid]; }
    __syncthreads();

    int warp = tid >> 5, lane = tid & 31;
    float b2A = b2s[lane], b2B = b2s[lane + 32];

    int nGroups = (N_NODES + 63) / 64;
    for (int g = blockIdx.x; g < nGroups; g += gridDim.x) {
        int rowBase = g * 64 + warp * 8;
        #pragma unroll
        for (int r = 0; r < 8; r++) {
            int row = rowBase + r;
            if (row < N_NODES && lane < 16) {
                float4 hv = ((const float4*)g_h)[(size_t)row * 16 + lane];
                float4 sc = ((const float4*)scs)[lane];
                float4 sh = ((const float4*)shs)[lane];
                float4 v;
                v.x = fmaxf(0.f, hv.x * sc.x + sh.x);
                v.y = fmaxf(0.f, hv.y * sc.y + sh.y);
                v.z = fmaxf(0.f, hv.z * sc.z + sh.z);
                v.w = fmaxf(0.f, hv.w * sc.w + sh.w);
                *(float4*)&st[warp][r * 64 + lane * 4] = v;
            }
        }
        __syncwarp();

        ull accA[8], accB[8];
        #pragma unroll
        for (int r = 0; r < 8; r++) {
            PACK2(accA[r], b2A, 0.f);
            PACK2(accB[r], b2B, 0.f);
        }
        #pragma unroll 4
        for (int kq = 0; kq < 16; kq++) {
            ull wA0 = *(const ull*)&WpA[(2 * kq) * 32 + lane];
            ull wB0 = *(const ull*)&WpB[(2 * kq) * 32 + lane];
            ull wA1 = *(const ull*)&WpA[(2 * kq + 1) * 32 + lane];
            ull wB1 = *(const ull*)&WpB[(2 * kq + 1) * 32 + lane];
            #pragma unroll
            for (int r = 0; r < 8; r++) {
                float4 a4 = *(const float4*)&st[warp][r * 64 + kq * 4];
                ull a01, a23;
                PACK2(a01, a4.x, a4.y);
                PACK2(a23, a4.z, a4.w);
                FMA2(accA[r], a01, wA0);
                FMA2(accB[r], a01, wB0);
                FMA2(accA[r], a23, wA1);
                FMA2(accB[r], a23, wB1);
            }
        }
        #pragma unroll
        for (int r = 0; r < 8; r++) {
            int row = rowBase + r;
            if (row < N_NODES) {
                float lA, hA, lB, hB;
                UNPACK2(lA, hA, accA[r]);
                UNPACK2(lB, hB, accB[r]);
                out[(size_t)row * 64 + lane] = lA + hA;
                out[(size_t)row * 64 + 32 + lane] = lB + hB;
            }
        }
        __syncwarp();
    }
}

// ---------------- launch ----------------
extern "C" void kernel_launch(void* const* d_in, const int* in_sizes, int n_in,
                              void* d_out, int out_size) {
    const float* x     = (const float*)d_in[0];
    const int* ei      = (const int*)d_in[1];
    const float* ea    = (const float*)d_in[2];
    const float* We    = (const float*)d_in[3];
    const float* be    = (const float*)d_in[4];
    const float* W1    = (const float*)d_in[5];
    const float* b1    = (const float*)d_in[6];
    const float* gamma = (const float*)d_in[7];
    const float* beta  = (const float*)d_in[8];
    const float* W2    = (const float*)d_in[9];
    const float* b2    = (const float*)d_in[10];
    float* out         = (float*)d_out;

    zero_kernel<<<1024, 256>>>();
    prep_kernel<<<1, 256>>>(We, be, W1, W2);

    hist_kernel<<<(N_EDGES + 255) / 256, 256>>>(ei);
    scan1_kernel<<<256, 256>>>();
    scan2_kernel<<<1, 256>>>();
    scan3_kernel<<<256, 256>>>();
    scatter_kernel<<<(N_EDGES + 255) / 256, 256>>>(ei);

    ea_kernel<<<(N_EDGES / 4 + 7) / 8, 256>>>(ei, (const float4*)ea);
    gather_x_kernel<<<(N_NODES * 32 + 255) / 256, 256>>>((const float4*)x);

    node_h_kernel<<<444, 256>>>(x, b1);
    bn_kernel<<<1, 64>>>(gamma, beta);
    node_out_kernel<<<444, 256>>>(b2, out);
}

// round 14
// speedup vs baseline: 1.6393x; 1.1595x over previous
#include <cuda_runtime.h>

#define N_NODES 50000
#define N_EDGES 800000
#define D_IN 64
#define D_OUT 64
#define E_DIM 32
#define NK 96
#define BN_EPS 1e-5f

typedef unsigned long long ull;

#define FMA2(acc, a, b) \
    asm("fma.rn.f32x2 %0, %1, %2, %3;" : "=l"(acc) : "l"(a), "l"(b), "l"(acc))
#define PACK2(out, lo, hi) \
    asm("mov.b64 %0, {%1, %2};" : "=l"(out) : "f"(lo), "f"(hi))
#define UNPACK2(lo, hi, in) \
    asm("mov.b64 {%0, %1}, %2;" : "=f"(lo), "=f"(hi) : "l"(in))

// ---------------- scratch ----------------
__device__ __align__(16) float g_aggX[N_NODES * D_IN];
__device__ __align__(16) float g_aggE[N_NODES * E_DIM];
__device__ __align__(16) float g_h[N_NODES * D_OUT];
__device__ int g_cnt[N_NODES];
__device__ int g_locpre[65536];
__device__ int g_part[256];
__device__ int g_partoff[256];
__device__ int g_rowstart[N_NODES + 1];
__device__ int g_cursor[N_NODES];
__device__ int g_esrc[N_EDGES];
__device__ __align__(16) float g_sum[D_OUT];
__device__ __align__(16) float g_sumsq[D_OUT];
__device__ __align__(8) float2 g_WpA[48 * 32];
__device__ __align__(8) float2 g_WpB[48 * 32];
__device__ __align__(8) float2 g_W2pA[32 * 32];
__device__ __align__(8) float2 g_W2pB[32 * 32];
__device__ __align__(16) float g_c2[D_OUT];
__device__ __align__(16) float g_scale[D_OUT];
__device__ __align__(16) float g_shift[D_OUT];

// ---------------- zero: branch-A part (cnt + stats) ----------------
__global__ void zero_cnt_kernel() {
    int idx = blockIdx.x * blockDim.x + threadIdx.x;
    int stride = gridDim.x * blockDim.x;
    for (int i = idx; i < N_NODES; i += stride) g_cnt[i] = 0;
    if (idx < D_OUT) { g_sum[idx] = 0.f; g_sumsq[idx] = 0.f; }
}

// ---------------- zero: branch-B part (aggE) ----------------
__global__ void zero_aggE_kernel() {
    int idx = blockIdx.x * blockDim.x + threadIdx.x;
    int stride = gridDim.x * blockDim.x;
    float4 z = make_float4(0.f, 0.f, 0.f, 0.f);
    for (int i = idx; i < N_NODES * (E_DIM / 4); i += stride) ((float4*)g_aggE)[i] = z;
}

// ---------------- prep packed weights (R13-proven) ----------------
__global__ void prep_kernel(const float* __restrict__ We,
                            const float* __restrict__ be,
                            const float* __restrict__ W1,
                            const float* __restrict__ W2) {
    __shared__ float W1s[D_IN * D_OUT];
    __shared__ float C1s[E_DIM * D_OUT];
    int tid = threadIdx.x;
    for (int i = tid; i < D_IN * D_OUT; i += 256) W1s[i] = W1[i];
    __syncthreads();
    for (int i = tid; i < E_DIM * D_OUT; i += 256) {
        int kk = i >> 6, d = i & 63;
        float s = 0.f;
        #pragma unroll 8
        for (int m = 0; m < D_IN; m++) s += We[kk * D_IN + m] * W1s[m * D_OUT + d];
        C1s[i] = s;
    }
    __syncthreads();
    for (int i = tid; i < 48 * 32; i += 256) {
        int k2 = i >> 5, l = i & 31;
        int ka = 2 * k2, kb = 2 * k2 + 1;
        float a0 = (ka < 64) ? W1s[ka * 64 + l] : C1s[(ka - 64) * 64 + l];
        float a1 = (kb < 64) ? W1s[kb * 64 + l] : C1s[(kb - 64) * 64 + l];
        g_WpA[i] = make_float2(a0, a1);
        float b0 = (ka < 64) ? W1s[ka * 64 + l + 32] : C1s[(ka - 64) * 64 + l + 32];
        float b1v = (kb < 64) ? W1s[kb * 64 + l + 32] : C1s[(kb - 64) * 64 + l + 32];
        g_WpB[i] = make_float2(b0, b1v);
    }
    for (int i = tid; i < 32 * 32; i += 256) {
        int k2 = i >> 5, l = i & 31;
        g_W2pA[i] = make_float2(W2[(2 * k2) * 64 + l], W2[(2 * k2 + 1) * 64 + l]);
        g_W2pB[i] = make_float2(W2[(2 * k2) * 64 + l + 32], W2[(2 * k2 + 1) * 64 + l + 32]);
    }
    if (tid < D_OUT) {
        float s = 0.f;
        #pragma unroll 8
        for (int m = 0; m < D_IN; m++) s += be[m] * W1s[m * D_OUT + tid];
        g_c2[tid] = s;
    }
}

// ---------------- CSR build (R13-proven) ----------------
__global__ void hist_kernel(const int* __restrict__ ei) {
    int e = blockIdx.x * blockDim.x + threadIdx.x;
    if (e < N_EDGES) atomicAdd(&g_cnt[ei[N_EDGES + e]], 1);
}

__global__ void scan1_kernel() {
    __shared__ int sd[256];
    int t = threadIdx.x;
    int g = blockIdx.x * 256 + t;
    int v = (g < N_NODES) ? g_cnt[g] : 0;
    sd[t] = v;
    __syncthreads();
    #pragma unroll
    for (int off = 1; off < 256; off <<= 1) {
        int y = (t >= off) ? sd[t - off] : 0;
        __syncthreads();
        sd[t] += y;
        __syncthreads();
    }
    g_locpre[g] = sd[t] - v;
    if (t == 255) g_part[blockIdx.x] = sd[255];
}

__global__ void scan2_kernel() {
    __shared__ int sd[256];
    int t = threadIdx.x;
    int v = g_part[t];
    sd[t] = v;
    __syncthreads();
    #pragma unroll
    for (int off = 1; off < 256; off <<= 1) {
        int y = (t >= off) ? sd[t - off] : 0;
        __syncthreads();
        sd[t] += y;
        __syncthreads();
    }
    g_partoff[t] = sd[t] - v;
}

__global__ void scan3_kernel() {
    int t = threadIdx.x;
    int g = blockIdx.x * 256 + t;
    if (g < N_NODES) {
        int rs = g_locpre[g] + g_partoff[blockIdx.x];
        g_rowstart[g] = rs;
        g_cursor[g] = rs;
    }
    if (g == 0) g_rowstart[N_NODES] = N_EDGES;
}

__global__ void scatter_kernel(const int* __restrict__ ei) {
    int e = blockIdx.x * blockDim.x + threadIdx.x;
    if (e >= N_EDGES) return;
    int dst = ei[N_EDGES + e];
    int pos = atomicAdd(&g_cursor[dst], 1);
    g_esrc[pos] = ei[e];
}

// ---------------- ea scatter (R13-proven) ----------------
__global__ void ea_kernel(const int* __restrict__ ei,
                          const float4* __restrict__ ea4) {
    int gwarp = (blockIdx.x * blockDim.x + threadIdx.x) >> 5;
    int lane = threadIdx.x & 31;
    int e = gwarp * 4 + (lane >> 3);
    if (e >= N_EDGES) return;
    int li = lane & 7;
    int dst = __ldg(&ei[N_EDGES + e]);
    float4 av = __ldg(&ea4[(size_t)e * (E_DIM / 4) + li]);
    atomicAdd(((float4*)(g_aggE + (size_t)dst * E_DIM)) + li, av);
}

// ---------------- gather x (R13-proven) ----------------
__global__ void gather_x_kernel(const float4* __restrict__ x4) {
    int gw = (blockIdx.x * blockDim.x + threadIdx.x) >> 5;
    if (gw >= N_NODES) return;
    int lane = threadIdx.x & 31;
    int half = lane >> 4, li = lane & 15;
    int start = g_rowstart[gw], end = g_rowstart[gw + 1];
    float4 acc = make_float4(0.f, 0.f, 0.f, 0.f);
    int p = start;
    for (; p + 8 <= end; p += 8) {
        int s0 = __ldg(&g_esrc[p + half]);
        int s1 = __ldg(&g_esrc[p + 2 + half]);
        int s2 = __ldg(&g_esrc[p + 4 + half]);
        int s3 = __ldg(&g_esrc[p + 6 + half]);
        float4 v0 = __ldg(&x4[(size_t)s0 * 16 + li]);
        float4 v1 = __ldg(&x4[(size_t)s1 * 16 + li]);
        float4 v2 = __ldg(&x4[(size_t)s2 * 16 + li]);
        float4 v3 = __ldg(&x4[(size_t)s3 * 16 + li]);
        acc.x += (v0.x + v1.x) + (v2.x + v3.x);
        acc.y += (v0.y + v1.y) + (v2.y + v3.y);
        acc.z += (v0.z + v1.z) + (v2.z + v3.z);
        acc.w += (v0.w + v1.w) + (v2.w + v3.w);
    }
    for (int e = p + half; e < end; e += 2) {
        int s = __ldg(&g_esrc[e]);
        float4 v = __ldg(&x4[(size_t)s * 16 + li]);
        acc.x += v.x; acc.y += v.y; acc.z += v.z; acc.w += v.w;
    }
    acc.x += __shfl_down_sync(0xffffffffu, acc.x, 16);
    acc.y += __shfl_down_sync(0xffffffffu, acc.y, 16);
    acc.z += __shfl_down_sync(0xffffffffu, acc.z, 16);
    acc.w += __shfl_down_sync(0xffffffffu, acc.w, 16);
    if (half == 0) ((float4*)g_aggX)[(size_t)gw * 16 + li] = acc;
}

// ---------------- node_h (R13-proven FFMA2) ----------------
__global__ __launch_bounds__(256, 3) void node_h_kernel(const float* __restrict__ x,
                                                        const float* __restrict__ b1) {
    __shared__ __align__(8) float2 WpA[48 * 32];
    __shared__ __align__(8) float2 WpB[48 * 32];
    __shared__ __align__(16) float st[8][8 * NK];
    __shared__ float c2s[64], b1s[64];
    __shared__ float bsum[64], bsq[64];

    int tid = threadIdx.x;
    for (int i = tid; i < 48 * 32; i += 256) { WpA[i] = g_WpA[i]; WpB[i] = g_WpB[i]; }
    if (tid < 64) { c2s[tid] = g_c2[tid]; b1s[tid] = b1[tid]; bsum[tid] = 0.f; bsq[tid] = 0.f; }
    __syncthreads();

    int warp = tid >> 5, lane = tid & 31;
    float c2A = c2s[lane], c2B = c2s[lane + 32];
    float b1A = b1s[lane], b1B = b1s[lane + 32];
    float s0 = 0.f, q0 = 0.f, s1 = 0.f, q1 = 0.f;

    int nGroups = (N_NODES + 63) / 64;
    for (int g = blockIdx.x; g < nGroups; g += gridDim.x) {
        int rowBase = g * 64 + warp * 8;
        #pragma unroll
        for (int r = 0; r < 8; r++) {
            int row = rowBase + r;
            if (row < N_NODES) {
                if (lane < 16) {
                    float4 a = ((const float4*)g_aggX)[(size_t)row * 16 + lane];
                    float4 xv = __ldg(&((const float4*)x)[(size_t)row * 16 + lane]);
                    a.x += xv.x; a.y += xv.y; a.z += xv.z; a.w += xv.w;
                    *(float4*)&st[warp][r * NK + lane * 4] = a;
                } else if (lane < 24) {
                    *(float4*)&st[warp][r * NK + 64 + (lane - 16) * 4] =
                        ((const float4*)g_aggE)[(size_t)row * 8 + (lane - 16)];
                }
            }
        }
        __syncwarp();

        ull accA[8], accB[8];
        #pragma unroll
        for (int r = 0; r < 8; r++) {
            int row = rowBase + r;
            float dg = 0.f;
            if (row < N_NODES) dg = (float)(g_rowstart[row + 1] - g_rowstart[row]);
            PACK2(accA[r], dg * c2A + b1A, 0.f);
            PACK2(accB[r], dg * c2B + b1B, 0.f);
        }
        #pragma unroll 4
        for (int kq = 0; kq < NK / 4; kq++) {
            ull wA0 = *(const ull*)&WpA[(2 * kq) * 32 + lane];
            ull wB0 = *(const ull*)&WpB[(2 * kq) * 32 + lane];
            ull wA1 = *(const ull*)&WpA[(2 * kq + 1) * 32 + lane];
            ull wB1 = *(const ull*)&WpB[(2 * kq + 1) * 32 + lane];
            #pragma unroll
            for (int r = 0; r < 8; r++) {
                float4 a4 = *(const float4*)&st[warp][r * NK + kq * 4];
                ull a01, a23;
                PACK2(a01, a4.x, a4.y);
                PACK2(a23, a4.z, a4.w);
                FMA2(accA[r], a01, wA0);
                FMA2(accB[r], a01, wB0);
                FMA2(accA[r], a23, wA1);
                FMA2(accB[r], a23, wB1);
            }
        }
        #pragma unroll
        for (int r = 0; r < 8; r++) {
            int row = rowBase + r;
            if (row < N_NODES) {
                float lA, hA, lB, hB;
                UNPACK2(lA, hA, accA[r]);
                UNPACK2(lB, hB, accB[r]);
                float h0 = lA + hA, h1 = lB + hB;
                g_h[(size_t)row * 64 + lane] = h0;
                g_h[(size_t)row * 64 + 32 + lane] = h1;
                s0 += h0; q0 += h0 * h0;
                s1 += h1; q1 += h1 * h1;
            }
        }
        __syncwarp();
    }
    atomicAdd(&bsum[lane], s0);      atomicAdd(&bsq[lane], q0);
    atomicAdd(&bsum[lane + 32], s1); atomicAdd(&bsq[lane + 32], q1);
    __syncthreads();
    if (tid < 64) { atomicAdd(&g_sum[tid], bsum[tid]); atomicAdd(&g_sumsq[tid], bsq[tid]); }
}

// ---------------- bn finalize ----------------
__global__ void bn_kernel(const float* __restrict__ gamma,
                          const float* __restrict__ beta) {
    int d = threadIdx.x;
    float n = (float)N_NODES;
    float mean = g_sum[d] / n;
    float var = g_sumsq[d] / n - mean * mean;
    float rstd = rsqrtf(var + BN_EPS);
    float sc = gamma[d] * rstd;
    g_scale[d] = sc;
    g_shift[d] = beta[d] - mean * sc;
}

// ---------------- node_out (R13-proven FFMA2) ----------------
__global__ __launch_bounds__(256, 3) void node_out_kernel(const float* __restrict__ b2,
                                                          float* __restrict__ out) {
    __shared__ __align__(8) float2 WpA[32 * 32];
    __shared__ __align__(8) float2 WpB[32 * 32];
    __shared__ __align__(16) float st[8][8 * 64];
    __shared__ __align__(16) float scs[64], shs[64];
    __shared__ float b2s[64];

    int tid = threadIdx.x;
    for (int i = tid; i < 32 * 32; i += 256) { WpA[i] = g_W2pA[i]; WpB[i] = g_W2pB[i]; }
    if (tid < 64) { scs[tid] = g_scale[tid]; shs[tid] = g_shift[tid]; b2s[tid] = b2[tid]; }
    __syncthreads();

    int warp = tid >> 5, lane = tid & 31;
    float b2A = b2s[lane], b2B = b2s[lane + 32];

    int nGroups = (N_NODES + 63) / 64;
    for (int g = blockIdx.x; g < nGroups; g += gridDim.x) {
        int rowBase = g * 64 + warp * 8;
        #pragma unroll
        for (int r = 0; r < 8; r++) {
            int row = rowBase + r;
            if (row < N_NODES && lane < 16) {
                float4 hv = ((const float4*)g_h)[(size_t)row * 16 + lane];
                float4 sc = ((const float4*)scs)[lane];
                float4 sh = ((const float4*)shs)[lane];
                float4 v;
                v.x = fmaxf(0.f, hv.x * sc.x + sh.x);
                v.y = fmaxf(0.f, hv.y * sc.y + sh.y);
                v.z = fmaxf(0.f, hv.z * sc.z + sh.z);
                v.w = fmaxf(0.f, hv.w * sc.w + sh.w);
                *(float4*)&st[warp][r * 64 + lane * 4] = v;
            }
        }
        __syncwarp();

        ull accA[8], accB[8];
        #pragma unroll
        for (int r = 0; r < 8; r++) {
            PACK2(accA[r], b2A, 0.f);
            PACK2(accB[r], b2B, 0.f);
        }
        #pragma unroll 4
        for (int kq = 0; kq < 16; kq++) {
            ull wA0 = *(const ull*)&WpA[(2 * kq) * 32 + lane];
            ull wB0 = *(const ull*)&WpB[(2 * kq) * 32 + lane];
            ull wA1 = *(const ull*)&WpA[(2 * kq + 1) * 32 + lane];
            ull wB1 = *(const ull*)&WpB[(2 * kq + 1) * 32 + lane];
            #pragma unroll
            for (int r = 0; r < 8; r++) {
                float4 a4 = *(const float4*)&st[warp][r * 64 + kq * 4];
                ull a01, a23;
                PACK2(a01, a4.x, a4.y);
                PACK2(a23, a4.z, a4.w);
                FMA2(accA[r], a01, wA0);
                FMA2(accB[r], a01, wB0);
                FMA2(accA[r], a23, wA1);
                FMA2(accB[r], a23, wB1);
            }
        }
        #pragma unroll
        for (int r = 0; r < 8; r++) {
            int row = rowBase + r;
            if (row < N_NODES) {
                float lA, hA, lB, hB;
                UNPACK2(lA, hA, accA[r]);
                UNPACK2(lB, hB, accB[r]);
                out[(size_t)row * 64 + lane] = lA + hA;
                out[(size_t)row * 64 + 32 + lane] = lB + hB;
            }
        }
        __syncwarp();
    }
}

// ---------------- launch: forked two-branch graph ----------------
extern "C" void kernel_launch(void* const* d_in, const int* in_sizes, int n_in,
                              void* d_out, int out_size) {
    const float* x     = (const float*)d_in[0];
    const int* ei      = (const int*)d_in[1];
    const float* ea    = (const float*)d_in[2];
    const float* We    = (const float*)d_in[3];
    const float* be    = (const float*)d_in[4];
    const float* W1    = (const float*)d_in[5];
    const float* b1    = (const float*)d_in[6];
    const float* gamma = (const float*)d_in[7];
    const float* beta  = (const float*)d_in[8];
    const float* W2    = (const float*)d_in[9];
    const float* b2    = (const float*)d_in[10];
    float* out         = (float*)d_out;

    // one-time host resources (host objects, not device memory)
    static cudaStream_t sB = [] {
        cudaStream_t s; cudaStreamCreateWithFlags(&s, cudaStreamNonBlocking); return s;
    }();
    static cudaEvent_t evFork = [] {
        cudaEvent_t e; cudaEventCreateWithFlags(&e, cudaEventDisableTiming); return e;
    }();
    static cudaEvent_t evJoin = [] {
        cudaEvent_t e; cudaEventCreateWithFlags(&e, cudaEventDisableTiming); return e;
    }();

    // fork
    cudaEventRecord(evFork, 0);
    cudaStreamWaitEvent(sB, evFork, 0);

    // Branch B (stream sB): aggE zero -> prep -> ea atomics
    zero_aggE_kernel<<<1024, 256, 0, sB>>>();
    prep_kernel<<<1, 256, 0, sB>>>(We, be, W1, W2);
    ea_kernel<<<(N_EDGES / 4 + 7) / 8, 256, 0, sB>>>(ei, (const float4*)ea);
    cudaEventRecord(evJoin, sB);

    // Branch A (stream 0): CSR build -> gather_x
    zero_cnt_kernel<<<256, 256>>>();
    hist_kernel<<<(N_EDGES + 255) / 256, 256>>>(ei);
    scan1_kernel<<<256, 256>>>();
    scan2_kernel<<<1, 256>>>();
    scan3_kernel<<<256, 256>>>();
    scatter_kernel<<<(N_EDGES + 255) / 256, 256>>>(ei);
    gather_x_kernel<<<(N_NODES * 32 + 255) / 256, 256>>>((const float4*)x);

    // join, then node pipeline
    cudaStreamWaitEvent(0, evJoin, 0);
    node_h_kernel<<<444, 256>>>(x, b1);
    bn_kernel<<<1, 64>>>(gamma, beta);
    node_out_kernel<<<444, 256>>>(b2, out);
}